// round 8
// baseline (speedup 1.0000x reference)
#include <cuda_runtime.h>
#include <math.h>

#define NB   128
#define NT   32
#define DZv  128
#define DFv  256
#define LOG2PI_F 1.8378770664093453f

typedef unsigned long long ull;

__device__ float g_Gf[NB * NB];
__device__ float g_partial[NT * 4];
__device__ int   g_count = 0;

static __device__ __forceinline__ ull fma2(ull a, ull b, ull c) {
    ull d;
    asm("fma.rn.f32x2 %0, %1, %2, %3;" : "=l"(d) : "l"(a), "l"(b), "l"(c));
    return d;
}
static __device__ __forceinline__ float ull_sum2(ull v) {
    union { ull u; float2 f; } w; w.u = v;
    return w.f.x + w.f.y;
}

// ---------------------------------------------------------------------------
// pair_f: f pairwise matrix with fused prep (exp + row constants inline).
// grid (4 i-chunks of 32, 8 j-chunks of 16), 256 threads.
// ---------------------------------------------------------------------------
__global__ void pair_f(const float* __restrict__ fm,
                       const float* __restrict__ flv,
                       const float* __restrict__ fs) {
    extern __shared__ float sm[];
    float2* st2 = (float2*)sm;             // 128*33 float2
    float*  As  = sm + 128 * 33 * 2;       // 16*260
    float*  Bs  = As + 16 * 260;           // 16*260
    float*  Csf = Bs + 16 * 260;           // 16

    const int tid = threadIdx.x;
    const int i0  = blockIdx.x * 32;
    const int j0  = blockIdx.y * 16;
    const int lane = tid & 31, wid = tid >> 5;

    // samples, d-pair-major: st2[d/2][i]
    for (int e = tid; e < 32 * DFv; e += 256) {
        int ii = e >> 8, d = e & 255;
        float v = fs[(i0 + ii) * DFv + d];
        ((float*)&st2[(d >> 1) * 33 + ii])[d & 1] = v;
    }
    // a/b tiles with fused exp
    for (int e = tid; e < 16 * DFv; e += 256) {
        int jj = e >> 8, d = e & 255;
        float lv = flv[(j0 + jj) * DFv + d];
        float a  = __expf(-lv);
        As[jj * 260 + d] = a;
        Bs[jj * 260 + d] = -fm[(j0 + jj) * DFv + d] * a;
    }
    // row constants: 8 warps x 2 rows
    for (int r = wid; r < 16; r += 8) {
        const float4* p = (const float4*)&flv[(j0 + r) * DFv + lane * 8];
        float4 v0 = p[0], v1 = p[1];
        float s = v0.x + v0.y + v0.z + v0.w + v1.x + v1.y + v1.z + v1.w;
        #pragma unroll
        for (int o = 16; o > 0; o >>= 1) s += __shfl_xor_sync(0xffffffffu, s, o);
        if (lane == 0) Csf[r] = 2.0f * s + (float)DFv * LOG2PI_F;
    }
    __syncthreads();

    const int i  = tid & 31;
    const int jj = tid >> 5;

    ull acc0 = 0ull, acc1 = 0ull;
    const ull* arow0 = (const ull*)&As[jj * 260];
    const ull* brow0 = (const ull*)&Bs[jj * 260];
    const ull* arow1 = (const ull*)&As[(jj + 8) * 260];
    const ull* brow1 = (const ull*)&Bs[(jj + 8) * 260];

    #pragma unroll 4
    for (int dp = 0; dp < DFv / 2; dp++) {
        ull s2 = ((const ull*)st2)[dp * 33 + i];
        ull t0 = fma2(s2, arow0[dp], brow0[dp]);
        acc0 = fma2(t0, t0, acc0);
        ull t1 = fma2(s2, arow1[dp], brow1[dp]);
        acc1 = fma2(t1, t1, acc1);
    }

    g_Gf[(i0 + i) * NB + j0 + jj]     = -0.5f * (ull_sum2(acc0) + Csf[jj]);
    g_Gf[(i0 + i) * NB + j0 + jj + 8] = -0.5f * (ull_sum2(acc1) + Csf[jj + 8]);
}

// ---------------------------------------------------------------------------
// k_z: fused prep + z pairwise + logsumexps + relu + final reduction.
// grid 128 (t = bid&31, i-chunk = bid>>5), 512 threads (16 warps).
// Warp ti: g = ti>>2 -> j = lane + 32g (distinct-row a/b loads);
//          im = ti&3 -> i = im + 4m, m in 0..7 (broadcast s loads).
// ---------------------------------------------------------------------------
__global__ void __launch_bounds__(512, 1)
k_z(const float* __restrict__ zm,
    const float* __restrict__ zlv,
    const float* __restrict__ zs,
    const int*   __restrict__ ntp,
    float*       __restrict__ out) {
    extern __shared__ float sm[];
    float* As = sm;                  // 128*132
    float* Bs = As + 128 * 132;      // 128*132
    float* Ss = Bs + 128 * 132;      // 32*132
    float* Cs = Ss + 32 * 132;       // 128
    float* Es = Cs + 128;            // 32*4*6 = 768 (also reused for final reduce)

    const int tid  = threadIdx.x;
    const int t    = blockIdx.x & 31;
    const int i0   = (blockIdx.x >> 5) * 32;
    const int lane = tid & 31;
    const int ti   = tid >> 5;           // 0..15
    const int g    = ti >> 2;            // j block
    const int im   = ti & 3;             // i sub-row
    const int j    = lane + 32 * g;

    // ---- staging with fused exp (coalesced 128B per warp) ----
    for (int e = tid; e < 128 * 128; e += 512) {
        int jj = e >> 7, dd = e & 127;
        int idx = jj * (NT * DZv) + t * DZv + dd;
        float lv = zlv[idx];
        float a  = __expf(-lv);
        As[jj * 132 + dd] = a;
        Bs[jj * 132 + dd] = -zm[idx] * a;
    }
    for (int e = tid; e < 32 * 32; e += 512) {
        int ii = e >> 5, dq = e & 31;
        *(float4*)&Ss[ii * 132 + dq * 4] =
            *(const float4*)&zs[(i0 + ii) * (NT * DZv) + t * DZv + dq * 4];
    }
    // row constants: 16 warps x 8 rows, lane covers d via float4
    for (int r = ti; r < 128; r += 16) {
        float4 v = *(const float4*)&zlv[r * (NT * DZv) + t * DZv + lane * 4];
        float s = v.x + v.y + v.z + v.w;
        #pragma unroll
        for (int o = 16; o > 0; o >>= 1) s += __shfl_xor_sync(0xffffffffu, s, o);
        if (lane == 0) Cs[r] = 2.0f * s + (float)DZv * LOG2PI_F;
    }
    __syncthreads();

    // ---- main loop ----
    ull acc[8][2];
    #pragma unroll
    for (int m = 0; m < 8; m++) { acc[m][0] = 0ull; acc[m][1] = 0ull; }

    const float* arow = &As[j * 132];
    const float* brow = &Bs[j * 132];

    #pragma unroll 4
    for (int d = 0; d < DZv; d += 4) {
        const ulonglong2 a2 = *(const ulonglong2*)&arow[d];
        const ulonglong2 b2 = *(const ulonglong2*)&brow[d];
        #pragma unroll
        for (int m = 0; m < 8; m++) {
            const ulonglong2 s2 = *(const ulonglong2*)&Ss[(im + 4 * m) * 132 + d];  // broadcast
            ull t0 = fma2(s2.x, a2.x, b2.x);
            acc[m][0] = fma2(t0, t0, acc[m][0]);
            ull t1 = fma2(s2.y, a2.y, b2.y);
            acc[m][1] = fma2(t1, t1, acc[m][1]);
        }
    }

    // ---- epilogue: per-warp partial logsumexps over this warp's 32 j ----
    const float lognorm = logf(128.0f) + logf((float)ntp[0]);
    const float cj = Cs[j];

    #pragma unroll
    for (int m = 0; m < 8; m++) {
        const int il = im + 4 * m;                   // local row 0..31
        float vz  = -0.5f * (ull_sum2(acc[m][0]) + ull_sum2(acc[m][1]) + cj);
        float vf  = g_Gf[(i0 + il) * NB + j];
        float vfz = vz + vf;

        float Mz = vz, Mf = vf, Mfz = vfz;
        #pragma unroll
        for (int o = 16; o > 0; o >>= 1) {
            Mz  = fmaxf(Mz,  __shfl_xor_sync(0xffffffffu, Mz,  o));
            Mf  = fmaxf(Mf,  __shfl_xor_sync(0xffffffffu, Mf,  o));
            Mfz = fmaxf(Mfz, __shfl_xor_sync(0xffffffffu, Mfz, o));
        }
        float Sz  = expf(vz  - Mz);
        float Sf  = expf(vf  - Mf);
        float Sfz = expf(vfz - Mfz);
        #pragma unroll
        for (int o = 16; o > 0; o >>= 1) {
            Sz  += __shfl_xor_sync(0xffffffffu, Sz,  o);
            Sf  += __shfl_xor_sync(0xffffffffu, Sf,  o);
            Sfz += __shfl_xor_sync(0xffffffffu, Sfz, o);
        }
        if (lane == 0) {
            float* e = &Es[(il * 4 + g) * 6];
            e[0] = Mz; e[1] = Sz; e[2] = Mf; e[3] = Sf; e[4] = Mfz; e[5] = Sfz;
        }
    }
    __syncthreads();

    // ---- combine 4 j-groups per row, relu, block sum ----
    if (tid < 32) {
        const float* e = &Es[tid * 24];
        float Mz = e[0], Mf = e[2], Mfz = e[4];
        #pragma unroll
        for (int q = 1; q < 4; q++) {
            Mz  = fmaxf(Mz,  e[q * 6 + 0]);
            Mf  = fmaxf(Mf,  e[q * 6 + 2]);
            Mfz = fmaxf(Mfz, e[q * 6 + 4]);
        }
        float Sz = 0.f, Sf = 0.f, Sfz = 0.f;
        #pragma unroll
        for (int q = 0; q < 4; q++) {
            Sz  += e[q * 6 + 1] * expf(e[q * 6 + 0] - Mz);
            Sf  += e[q * 6 + 3] * expf(e[q * 6 + 2] - Mf);
            Sfz += e[q * 6 + 5] * expf(e[q * 6 + 4] - Mfz);
        }
        float term = (Mfz + logf(Sfz)) - (Mf + logf(Sf)) - (Mz + logf(Sz)) + lognorm;
        float v = term > 0.0f ? term : 0.0f;
        #pragma unroll
        for (int o = 16; o > 0; o >>= 1) v += __shfl_xor_sync(0xffffffffu, v, o);
        if (tid == 0) g_partial[blockIdx.x] = v;
    }

    // ---- last block does the deterministic final reduction ----
    __shared__ int isLast;
    __threadfence();
    __syncthreads();
    if (tid == 0) isLast = (atomicAdd(&g_count, 1) == NT * 4 - 1);
    __syncthreads();
    if (isLast) {
        if (tid < 128) Es[tid] = g_partial[tid];
        __syncthreads();
        if (tid < 32) {
            float s = Es[tid] + Es[tid + 32] + Es[tid + 64] + Es[tid + 96];
            #pragma unroll
            for (int o = 16; o > 0; o >>= 1) s += __shfl_xor_sync(0xffffffffu, s, o);
            if (tid == 0) {
                out[0] = s * (1.0f / (float)(NT * NB));
                g_count = 0;
            }
        }
    }
}

// ---------------------------------------------------------------------------
extern "C" void kernel_launch(void* const* d_in, const int* in_sizes, int n_in,
                              void* d_out, int out_size) {
    const float* fm  = (const float*)d_in[0];
    const float* flv = (const float*)d_in[1];
    const float* fs  = (const float*)d_in[2];
    const float* zm  = (const float*)d_in[3];
    const float* zlv = (const float*)d_in[4];
    const float* zs  = (const float*)d_in[5];
    const int*   nt  = (const int*)  d_in[6];

    const size_t smem_pf = (size_t)(128 * 33 * 2 + 16 * 260 * 2 + 16) * sizeof(float);   // ~67 KB
    const size_t smem_kz = (size_t)(128 * 132 * 2 + 32 * 132 + 128 + 768) * sizeof(float); // ~156 KB

    static int inited = 0;
    if (!inited) {
        cudaFuncSetAttribute(pair_f, cudaFuncAttributeMaxDynamicSharedMemorySize, (int)smem_pf);
        cudaFuncSetAttribute(k_z,    cudaFuncAttributeMaxDynamicSharedMemorySize, (int)smem_kz);
        inited = 1;
    }

    pair_f<<<dim3(4, 8), 256, smem_pf>>>(fm, flv, fs);
    k_z<<<128, 512, smem_kz>>>(zm, zlv, zs, nt, (float*)d_out);
}

// round 10
// speedup vs baseline: 1.3893x; 1.3893x over previous
#include <cuda_runtime.h>
#include <math.h>

#define NB   128
#define NT   32
#define DZv  128
#define DFv  256
#define LOG2PI_F 1.8378770664093453f

typedef unsigned long long ull;

// ----- device scratch -------------------------------------------------------
__device__ float g_Gf[NB * NB];          // f pairwise log-density (final)
__device__ float g_fa[NB * DFv];         // exp(-f_logvar)
__device__ float g_fb[NB * DFv];         // -f_mean * fa
__device__ float g_Cf[NB];
__device__ float g_za[NB * NT * DZv];    // exp(-z_logvar)  [j][t][d]
__device__ float g_zb[NB * NT * DZv];    // -z_mean * za
__device__ float g_Cz[NT * NB];
__device__ float g_partial[NT * 4];
__device__ int   g_count = 0;

static __device__ __forceinline__ ull fma2(ull a, ull b, ull c) {
    ull d;
    asm("fma.rn.f32x2 %0, %1, %2, %3;" : "=l"(d) : "l"(a), "l"(b), "l"(c));
    return d;
}
static __device__ __forceinline__ float ull_sum2(ull v) {
    union { ull u; float2 f; } w; w.u = v;
    return w.f.x + w.f.y;
}

// ---------------------------------------------------------------------------
// prep_all: one launch, all exp transforms + row constants, each exp once.
// blocks [0,2048): z rows (2 rows of 128 per block).  [2048,2176): f rows.
// ---------------------------------------------------------------------------
__global__ void prep_all(const float* __restrict__ zm,
                         const float* __restrict__ zlv,
                         const float* __restrict__ fm,
                         const float* __restrict__ flv) {
    __shared__ float red[8];
    const int tid = threadIdx.x, lane = tid & 31, w = tid >> 5;
    const int bid = blockIdx.x;

    if (bid < 2048) {
        const int e = bid * 256 + tid;          // [j][t][d] flat
        const float lv = zlv[e];
        const float a  = __expf(-lv);
        g_za[e] = a;
        g_zb[e] = -zm[e] * a;
        float s = lv;
        #pragma unroll
        for (int o = 16; o > 0; o >>= 1) s += __shfl_xor_sync(0xffffffffu, s, o);
        if (lane == 0) red[w] = s;
        __syncthreads();
        if ((tid & 127) == 0) {
            const int wb = tid >> 5;           // 0 or 4
            float t4 = red[wb] + red[wb + 1] + red[wb + 2] + red[wb + 3];
            const int j = e >> 12, t = (e >> 7) & 31;
            g_Cz[t * NB + j] = 2.0f * t4 + (float)DZv * LOG2PI_F;
        }
    } else {
        const int j = bid - 2048, d = tid;
        const float lv = flv[j * DFv + d];
        const float a  = __expf(-lv);
        g_fa[j * DFv + d] = a;
        g_fb[j * DFv + d] = -fm[j * DFv + d] * a;
        float s = lv;
        #pragma unroll
        for (int o = 16; o > 0; o >>= 1) s += __shfl_xor_sync(0xffffffffu, s, o);
        if (lane == 0) red[w] = s;
        __syncthreads();
        if (tid == 0) {
            float t8 = 0.f;
            #pragma unroll
            for (int q = 0; q < 8; q++) t8 += red[q];
            g_Cf[j] = 2.0f * t8 + (float)DFv * LOG2PI_F;
        }
    }
}

// ---------------------------------------------------------------------------
// pair_f: f pairwise matrix from precomputed g_fa/g_fb.
// grid (4 i-chunks of 32, 8 j-chunks of 16), 256 threads.
// ---------------------------------------------------------------------------
__global__ void pair_f(const float* __restrict__ fs) {
    extern __shared__ float sm[];
    float2* st2 = (float2*)sm;             // 128*33 float2
    float*  As  = sm + 128 * 33 * 2;       // 16*260
    float*  Bs  = As + 16 * 260;           // 16*260

    const int tid = threadIdx.x;
    const int i0  = blockIdx.x * 32;
    const int j0  = blockIdx.y * 16;

    for (int e = tid; e < 32 * DFv; e += 256) {
        int ii = e >> 8, d = e & 255;
        float v = fs[(i0 + ii) * DFv + d];
        ((float*)&st2[(d >> 1) * 33 + ii])[d & 1] = v;
    }
    for (int e = tid; e < 16 * DFv; e += 256) {
        int jj = e >> 8, d = e & 255;
        As[jj * 260 + d] = g_fa[(j0 + jj) * DFv + d];
        Bs[jj * 260 + d] = g_fb[(j0 + jj) * DFv + d];
    }
    __syncthreads();

    const int i  = tid & 31;
    const int jj = tid >> 5;

    ull acc0 = 0ull, acc1 = 0ull;
    const ull* arow0 = (const ull*)&As[jj * 260];
    const ull* brow0 = (const ull*)&Bs[jj * 260];
    const ull* arow1 = (const ull*)&As[(jj + 8) * 260];
    const ull* brow1 = (const ull*)&Bs[(jj + 8) * 260];

    #pragma unroll 4
    for (int dp = 0; dp < DFv / 2; dp++) {
        ull s2 = ((const ull*)st2)[dp * 33 + i];
        ull t0 = fma2(s2, arow0[dp], brow0[dp]);
        acc0 = fma2(t0, t0, acc0);
        ull t1 = fma2(s2, arow1[dp], brow1[dp]);
        acc1 = fma2(t1, t1, acc1);
    }

    g_Gf[(i0 + i) * NB + j0 + jj]     = -0.5f * (ull_sum2(acc0) + g_Cf[j0 + jj]);
    g_Gf[(i0 + i) * NB + j0 + jj + 8] = -0.5f * (ull_sum2(acc1) + g_Cf[j0 + jj + 8]);
}

// ---------------------------------------------------------------------------
// k_z: z pairwise + logsumexps + relu + fused final reduction.
// grid 128 (t = bid&31, i-chunk = bid>>5), 512 threads = 16 warps.
// Warp w: h = w>>3 selects d-half (h*64..h*64+63); wq = w&7 is the R4 tile:
//   i in {wq + 8m} (m 0..3, broadcast s), j in {lane + 32k} (k 0..3).
// Warp pair (wq, wq+8) computes the same 4x4 tile over complementary d;
// partial sums combined through smem before the epilogue.
// ---------------------------------------------------------------------------
__global__ void __launch_bounds__(512, 1)
k_z(const float* __restrict__ zs,
    const int*   __restrict__ ntp,
    float*       __restrict__ out) {
    extern __shared__ float sm[];
    float* As = sm;                  // 128*132
    float* Bs = As + 128 * 132;      // 128*132
    float* Ss = Bs + 128 * 132;      // 32*132
    float* Cs = Ss + 32 * 132;       // 128
    float* Ws = Cs + 128;            // 8
    float* Xs = Ws + 8;              // 256*16 (half-combine + final reduce)

    const int tid  = threadIdx.x;
    const int t    = blockIdx.x & 31;
    const int i0   = (blockIdx.x >> 5) * 32;
    const int lane = tid & 31;
    const int w    = tid >> 5;           // 0..15
    const int h    = w >> 3;             // d-half
    const int wq   = w & 7;              // tile row-group

    // ---- staging (coalesced float4 from precomputed arrays) ----
    for (int e = tid; e < 128 * 32; e += 512) {
        int jj = e >> 5, dq = e & 31;
        *(float4*)&As[jj * 132 + dq * 4] = *(const float4*)&g_za[jj * (NT * DZv) + t * DZv + dq * 4];
        *(float4*)&Bs[jj * 132 + dq * 4] = *(const float4*)&g_zb[jj * (NT * DZv) + t * DZv + dq * 4];
    }
    for (int e = tid; e < 32 * 32; e += 512) {
        int ii = e >> 5, dq = e & 31;
        *(float4*)&Ss[ii * 132 + dq * 4] =
            *(const float4*)&zs[(i0 + ii) * (NT * DZv) + t * DZv + dq * 4];
    }
    if (tid < 128) Cs[tid] = g_Cz[t * NB + tid];
    __syncthreads();

    // ---- main loop over this warp's d-half ----
    ull acc[4][4][2];
    #pragma unroll
    for (int m = 0; m < 4; m++)
        #pragma unroll
        for (int k = 0; k < 4; k++) { acc[m][k][0] = 0ull; acc[m][k][1] = 0ull; }

    const int d0 = h * 64;
    #pragma unroll 4
    for (int dd = 0; dd < 64; dd += 4) {
        const int d = d0 + dd;
        ulonglong2 s2[4], a2[4], b2[4];
        #pragma unroll
        for (int m = 0; m < 4; m++)
            s2[m] = *(const ulonglong2*)&Ss[(wq + 8 * m) * 132 + d];    // broadcast
        #pragma unroll
        for (int k = 0; k < 4; k++) {
            a2[k] = *(const ulonglong2*)&As[(lane + 32 * k) * 132 + d];
            b2[k] = *(const ulonglong2*)&Bs[(lane + 32 * k) * 132 + d];
        }
        #pragma unroll
        for (int m = 0; m < 4; m++) {
            #pragma unroll
            for (int k = 0; k < 4; k++) {
                ull t0 = fma2(s2[m].x, a2[k].x, b2[k].x);
                acc[m][k][0] = fma2(t0, t0, acc[m][k][0]);
                ull t1 = fma2(s2[m].y, a2[k].y, b2[k].y);
                acc[m][k][1] = fma2(t1, t1, acc[m][k][1]);
            }
        }
    }

    // reduce packed lanes to scalar per tile element
    float sums[4][4];
    #pragma unroll
    for (int m = 0; m < 4; m++)
        #pragma unroll
        for (int k = 0; k < 4; k++)
            sums[m][k] = ull_sum2(acc[m][k][0]) + ull_sum2(acc[m][k][1]);

    // ---- combine d-halves through smem ----
    if (h == 1) {
        float* x = &Xs[(tid - 256) * 16];
        #pragma unroll
        for (int m = 0; m < 4; m++)
            #pragma unroll
            for (int k = 0; k < 4; k++) x[m * 4 + k] = sums[m][k];
    }
    __syncthreads();

    if (h == 0) {
        const float* x = &Xs[tid * 16];
        #pragma unroll
        for (int m = 0; m < 4; m++)
            #pragma unroll
            for (int k = 0; k < 4; k++) sums[m][k] += x[m * 4 + k];

        // ---- epilogue: per-row logsumexps (row group in one warp) ----
        const float lognorm = logf(128.0f) + logf((float)ntp[0]);
        float tsum = 0.0f;

        #pragma unroll
        for (int m = 0; m < 4; m++) {
            const int gi = i0 + wq + 8 * m;
            float vz[4], vf[4], vfz[4];
            #pragma unroll
            for (int k = 0; k < 4; k++) {
                int j = lane + 32 * k;
                vz[k]  = -0.5f * (sums[m][k] + Cs[j]);
                vf[k]  = g_Gf[gi * NB + j];
                vfz[k] = vz[k] + vf[k];
            }
            float Mz  = fmaxf(fmaxf(vz[0],  vz[1]),  fmaxf(vz[2],  vz[3]));
            float Mf  = fmaxf(fmaxf(vf[0],  vf[1]),  fmaxf(vf[2],  vf[3]));
            float Mfz = fmaxf(fmaxf(vfz[0], vfz[1]), fmaxf(vfz[2], vfz[3]));
            #pragma unroll
            for (int o = 16; o > 0; o >>= 1) {
                Mz  = fmaxf(Mz,  __shfl_xor_sync(0xffffffffu, Mz,  o));
                Mf  = fmaxf(Mf,  __shfl_xor_sync(0xffffffffu, Mf,  o));
                Mfz = fmaxf(Mfz, __shfl_xor_sync(0xffffffffu, Mfz, o));
            }
            float Sz  = expf(vz[0]  - Mz)  + expf(vz[1]  - Mz)  + expf(vz[2]  - Mz)  + expf(vz[3]  - Mz);
            float Sf  = expf(vf[0]  - Mf)  + expf(vf[1]  - Mf)  + expf(vf[2]  - Mf)  + expf(vf[3]  - Mf);
            float Sfz = expf(vfz[0] - Mfz) + expf(vfz[1] - Mfz) + expf(vfz[2] - Mfz) + expf(vfz[3] - Mfz);
            #pragma unroll
            for (int o = 16; o > 0; o >>= 1) {
                Sz  += __shfl_xor_sync(0xffffffffu, Sz,  o);
                Sf  += __shfl_xor_sync(0xffffffffu, Sf,  o);
                Sfz += __shfl_xor_sync(0xffffffffu, Sfz, o);
            }
            float term = (Mfz + logf(Sfz)) - (Mf + logf(Sf)) - (Mz + logf(Sz)) + lognorm;
            if (term > 0.0f) tsum += term;
        }

        if (lane == 0) Ws[wq] = tsum;
    }
    __syncthreads();
    if (tid == 0) {
        float s = 0.0f;
        #pragma unroll
        for (int q = 0; q < 8; q++) s += Ws[q];
        g_partial[blockIdx.x] = s;
    }

    // ---- last block: deterministic final reduction ----
    __shared__ int isLast;
    __threadfence();
    __syncthreads();
    if (tid == 0) isLast = (atomicAdd(&g_count, 1) == NT * 4 - 1);
    __syncthreads();
    if (isLast) {
        if (tid < 128) Xs[tid] = g_partial[tid];
        __syncthreads();
        if (tid < 32) {
            float s = Xs[tid] + Xs[tid + 32] + Xs[tid + 64] + Xs[tid + 96];
            #pragma unroll
            for (int o = 16; o > 0; o >>= 1) s += __shfl_xor_sync(0xffffffffu, s, o);
            if (tid == 0) {
                out[0] = s * (1.0f / (float)(NT * NB));
                g_count = 0;
            }
        }
    }
}

// ---------------------------------------------------------------------------
extern "C" void kernel_launch(void* const* d_in, const int* in_sizes, int n_in,
                              void* d_out, int out_size) {
    const float* fm  = (const float*)d_in[0];
    const float* flv = (const float*)d_in[1];
    const float* fs  = (const float*)d_in[2];
    const float* zm  = (const float*)d_in[3];
    const float* zlv = (const float*)d_in[4];
    const float* zs  = (const float*)d_in[5];
    const int*   nt  = (const int*)  d_in[6];

    const size_t smem_pf = (size_t)(128 * 33 * 2 + 16 * 260 * 2) * sizeof(float);              // ~50 KB
    const size_t smem_kz = (size_t)(128 * 132 * 2 + 32 * 132 + 128 + 8 + 256 * 16) * sizeof(float); // ~169 KB

    static int inited = 0;
    if (!inited) {
        cudaFuncSetAttribute(pair_f, cudaFuncAttributeMaxDynamicSharedMemorySize, (int)smem_pf);
        cudaFuncSetAttribute(k_z,    cudaFuncAttributeMaxDynamicSharedMemorySize, (int)smem_kz);
        inited = 1;
    }

    prep_all<<<2176, 256>>>(zm, zlv, fm, flv);
    pair_f<<<dim3(4, 8), 256, smem_pf>>>(fs);
    k_z<<<128, 512, smem_kz>>>(zs, nt, (float*)d_out);
}

// round 11
// speedup vs baseline: 1.4486x; 1.0427x over previous
#include <cuda_runtime.h>
#include <math.h>

#define NB   128
#define NT   32
#define DZv  128
#define DFv  256
#define LOG2PI_F 1.8378770664093453f

typedef unsigned long long ull;

// ----- device scratch -------------------------------------------------------
__device__ float g_Gf[NB * NB];          // f pairwise log-density (final)
__device__ float g_fa[NB * DFv];         // exp(-f_logvar)
__device__ float g_fb[NB * DFv];         // -f_mean * fa
__device__ float g_Cf[NB];
__device__ float g_za[NT * NB * DZv];    // exp(-z_logvar)   [t][j][d]
__device__ float g_zb[NT * NB * DZv];    // -z_mean * za     [t][j][d]
__device__ float g_Cz[NT * NB];
__device__ float g_partial[NT * 4];
__device__ int   g_count = 0;

static __device__ __forceinline__ ull fma2(ull a, ull b, ull c) {
    ull d;
    asm("fma.rn.f32x2 %0, %1, %2, %3;" : "=l"(d) : "l"(a), "l"(b), "l"(c));
    return d;
}
static __device__ __forceinline__ float ull_sum2(ull v) {
    union { ull u; float2 f; } w; w.u = v;
    return w.f.x + w.f.y;
}

// ---------------------------------------------------------------------------
// prep_all: all exp transforms + row constants, float4 per thread.
// blocks [0,512): z rows, 8 rows (j,t) per block (warp per row).
// blocks [512,544): f rows, 4 rows per block (2 warps per row).
// ---------------------------------------------------------------------------
__global__ void prep_all(const float* __restrict__ zm,
                         const float* __restrict__ zlv,
                         const float* __restrict__ fm,
                         const float* __restrict__ flv) {
    __shared__ float red[8];
    const int tid = threadIdx.x, lane = tid & 31, w = tid >> 5;
    const int bid = blockIdx.x;

    if (bid < 512) {
        // z: row r = bid*8 + w over [j][t] input order
        const int r = bid * 8 + w;          // j = r>>5, t = r&31
        const int j = r >> 5, t = r & 31;
        const int ein  = r * DZv + lane * 4;             // input  [j][t][d]
        const int eout = t * (NB * DZv) + j * DZv + lane * 4;  // output [t][j][d]
        float4 lv = *(const float4*)&zlv[ein];
        float4 mu = *(const float4*)&zm[ein];
        float4 a, b;
        a.x = __expf(-lv.x); a.y = __expf(-lv.y); a.z = __expf(-lv.z); a.w = __expf(-lv.w);
        b.x = -mu.x * a.x;   b.y = -mu.y * a.y;   b.z = -mu.z * a.z;   b.w = -mu.w * a.w;
        *(float4*)&g_za[eout] = a;
        *(float4*)&g_zb[eout] = b;
        float s = lv.x + lv.y + lv.z + lv.w;
        #pragma unroll
        for (int o = 16; o > 0; o >>= 1) s += __shfl_xor_sync(0xffffffffu, s, o);
        if (lane == 0) g_Cz[t * NB + j] = 2.0f * s + (float)DZv * LOG2PI_F;
    } else {
        // f: row j = (bid-512)*4 + w/2; half = w&1 covers 128 d each
        const int j = (bid - 512) * 4 + (w >> 1);
        const int d = (w & 1) * 128 + lane * 4;
        const int e = j * DFv + d;
        float4 lv = *(const float4*)&flv[e];
        float4 mu = *(const float4*)&fm[e];
        float4 a, b;
        a.x = __expf(-lv.x); a.y = __expf(-lv.y); a.z = __expf(-lv.z); a.w = __expf(-lv.w);
        b.x = -mu.x * a.x;   b.y = -mu.y * a.y;   b.z = -mu.z * a.z;   b.w = -mu.w * a.w;
        *(float4*)&g_fa[e] = a;
        *(float4*)&g_fb[e] = b;
        float s = lv.x + lv.y + lv.z + lv.w;
        #pragma unroll
        for (int o = 16; o > 0; o >>= 1) s += __shfl_xor_sync(0xffffffffu, s, o);
        if (lane == 0) red[w] = s;
        __syncthreads();
        if (lane == 0 && (w & 1) == 0) {
            float t2 = red[w] + red[w + 1];
            g_Cf[j] = 2.0f * t2 + (float)DFv * LOG2PI_F;
        }
    }
}

// ---------------------------------------------------------------------------
// pair_f: f pairwise matrix. grid (8 i-chunks of 16, 8 j-chunks of 16) = 64
// blocks, 256 threads: i = tid&15, jj = tid>>4 — one output each.
// smem: st2[128][17] float2 (d-pair-major samples for 16 i), As/Bs[16][260].
// ---------------------------------------------------------------------------
__global__ void pair_f(const float* __restrict__ fs) {
    extern __shared__ float sm[];
    float2* st2 = (float2*)sm;             // 128*17 float2 = 4352 floats
    float*  As  = sm + 128 * 17 * 2;       // 16*260
    float*  Bs  = As + 16 * 260;           // 16*260

    const int tid = threadIdx.x;
    const int i0  = blockIdx.x * 16;
    const int j0  = blockIdx.y * 16;

    // samples d-pair-major: st2[d/2][i]
    for (int e = tid; e < 16 * DFv; e += 256) {
        int ii = e >> 8, d = e & 255;
        float v = fs[(i0 + ii) * DFv + d];
        ((float*)&st2[(d >> 1) * 17 + ii])[d & 1] = v;
    }
    for (int e = tid; e < 16 * DFv; e += 256) {
        int jj = e >> 8, d = e & 255;
        As[jj * 260 + d] = g_fa[(j0 + jj) * DFv + d];
        Bs[jj * 260 + d] = g_fb[(j0 + jj) * DFv + d];
    }
    __syncthreads();

    const int i  = tid & 15;
    const int jj = tid >> 4;

    ull acc = 0ull;
    const ull* arow = (const ull*)&As[jj * 260];
    const ull* brow = (const ull*)&Bs[jj * 260];

    #pragma unroll 8
    for (int dp = 0; dp < DFv / 2; dp++) {
        ull s2 = ((const ull*)st2)[dp * 17 + i];
        ull t0 = fma2(s2, arow[dp], brow[dp]);
        acc = fma2(t0, t0, acc);
    }

    g_Gf[(i0 + i) * NB + j0 + jj] = -0.5f * (ull_sum2(acc) + g_Cf[j0 + jj]);
}

// ---------------------------------------------------------------------------
// k_z: z pairwise + logsumexps + relu + fused final reduction.
// grid 128 (t = bid&31, i-chunk = bid>>5), 512 threads = 16 warps.
// Warp w: h = w>>3 selects d-half; wq = w&7:
//   i in {wq + 8m} (broadcast s), j = lane + 32k (distinct a/b rows).
// Warp pair (wq, wq+8) combines complementary d-halves through smem.
// ---------------------------------------------------------------------------
__global__ void __launch_bounds__(512, 1)
k_z(const float* __restrict__ zs,
    const int*   __restrict__ ntp,
    float*       __restrict__ out) {
    extern __shared__ float sm[];
    float* As = sm;                  // 128*132
    float* Bs = As + 128 * 132;      // 128*132
    float* Ss = Bs + 128 * 132;      // 32*132
    float* Cs = Ss + 32 * 132;       // 128
    float* Ws = Cs + 128;            // 8
    float* Xs = Ws + 8;              // 256*16 (half-combine + final reduce)
    float* Gs = Xs + 256 * 16;       // 32*128 (Gf tile)

    const int tid  = threadIdx.x;
    const int t    = blockIdx.x & 31;
    const int i0   = (blockIdx.x >> 5) * 32;
    const int lane = tid & 31;
    const int w    = tid >> 5;           // 0..15
    const int h    = w >> 3;             // d-half
    const int wq   = w & 7;              // tile row-group

    // ---- staging: fully contiguous [t][j][d] slabs ----
    const float* zaT = &g_za[t * (NB * DZv)];
    const float* zbT = &g_zb[t * (NB * DZv)];
    for (int e = tid; e < 128 * 32; e += 512) {
        int jj = e >> 5, dq = e & 31;
        *(float4*)&As[jj * 132 + dq * 4] = *(const float4*)&zaT[jj * DZv + dq * 4];
        *(float4*)&Bs[jj * 132 + dq * 4] = *(const float4*)&zbT[jj * DZv + dq * 4];
    }
    for (int e = tid; e < 32 * 32; e += 512) {
        int ii = e >> 5, dq = e & 31;
        *(float4*)&Ss[ii * 132 + dq * 4] =
            *(const float4*)&zs[(i0 + ii) * (NT * DZv) + t * DZv + dq * 4];
    }
    // Gf tile for this i-chunk (contiguous 16KB)
    for (int e = tid; e < 32 * 32; e += 512) {
        *(float4*)&Gs[e * 4] = *(const float4*)&g_Gf[i0 * NB + e * 4];
    }
    if (tid < 128) Cs[tid] = g_Cz[t * NB + tid];
    __syncthreads();

    // ---- main loop over this warp's d-half ----
    ull acc[4][4][2];
    #pragma unroll
    for (int m = 0; m < 4; m++)
        #pragma unroll
        for (int k = 0; k < 4; k++) { acc[m][k][0] = 0ull; acc[m][k][1] = 0ull; }

    const int d0 = h * 64;
    #pragma unroll 4
    for (int dd = 0; dd < 64; dd += 4) {
        const int d = d0 + dd;
        ulonglong2 s2[4], a2[4], b2[4];
        #pragma unroll
        for (int m = 0; m < 4; m++)
            s2[m] = *(const ulonglong2*)&Ss[(wq + 8 * m) * 132 + d];    // broadcast
        #pragma unroll
        for (int k = 0; k < 4; k++) {
            a2[k] = *(const ulonglong2*)&As[(lane + 32 * k) * 132 + d];
            b2[k] = *(const ulonglong2*)&Bs[(lane + 32 * k) * 132 + d];
        }
        #pragma unroll
        for (int m = 0; m < 4; m++) {
            #pragma unroll
            for (int k = 0; k < 4; k++) {
                ull t0 = fma2(s2[m].x, a2[k].x, b2[k].x);
                acc[m][k][0] = fma2(t0, t0, acc[m][k][0]);
                ull t1 = fma2(s2[m].y, a2[k].y, b2[k].y);
                acc[m][k][1] = fma2(t1, t1, acc[m][k][1]);
            }
        }
    }

    float sums[4][4];
    #pragma unroll
    for (int m = 0; m < 4; m++)
        #pragma unroll
        for (int k = 0; k < 4; k++)
            sums[m][k] = ull_sum2(acc[m][k][0]) + ull_sum2(acc[m][k][1]);

    // ---- combine d-halves through smem ----
    if (h == 1) {
        float* x = &Xs[(tid - 256) * 16];
        #pragma unroll
        for (int m = 0; m < 4; m++)
            #pragma unroll
            for (int k = 0; k < 4; k++) x[m * 4 + k] = sums[m][k];
    }
    __syncthreads();

    if (h == 0) {
        const float* x = &Xs[tid * 16];
        #pragma unroll
        for (int m = 0; m < 4; m++)
            #pragma unroll
            for (int k = 0; k < 4; k++) sums[m][k] += x[m * 4 + k];

        // ---- epilogue: per-row logsumexps (row group in one warp) ----
        const float lognorm = logf(128.0f) + logf((float)ntp[0]);
        float tsum = 0.0f;

        #pragma unroll
        for (int m = 0; m < 4; m++) {
            const int il = wq + 8 * m;
            float vz[4], vf[4], vfz[4];
            #pragma unroll
            for (int k = 0; k < 4; k++) {
                int j = lane + 32 * k;
                vz[k]  = -0.5f * (sums[m][k] + Cs[j]);
                vf[k]  = Gs[il * NB + j];
                vfz[k] = vz[k] + vf[k];
            }
            float Mz  = fmaxf(fmaxf(vz[0],  vz[1]),  fmaxf(vz[2],  vz[3]));
            float Mf  = fmaxf(fmaxf(vf[0],  vf[1]),  fmaxf(vf[2],  vf[3]));
            float Mfz = fmaxf(fmaxf(vfz[0], vfz[1]), fmaxf(vfz[2], vfz[3]));
            #pragma unroll
            for (int o = 16; o > 0; o >>= 1) {
                Mz  = fmaxf(Mz,  __shfl_xor_sync(0xffffffffu, Mz,  o));
                Mf  = fmaxf(Mf,  __shfl_xor_sync(0xffffffffu, Mf,  o));
                Mfz = fmaxf(Mfz, __shfl_xor_sync(0xffffffffu, Mfz, o));
            }
            float Sz  = expf(vz[0]  - Mz)  + expf(vz[1]  - Mz)  + expf(vz[2]  - Mz)  + expf(vz[3]  - Mz);
            float Sf  = expf(vf[0]  - Mf)  + expf(vf[1]  - Mf)  + expf(vf[2]  - Mf)  + expf(vf[3]  - Mf);
            float Sfz = expf(vfz[0] - Mfz) + expf(vfz[1] - Mfz) + expf(vfz[2] - Mfz) + expf(vfz[3] - Mfz);
            #pragma unroll
            for (int o = 16; o > 0; o >>= 1) {
                Sz  += __shfl_xor_sync(0xffffffffu, Sz,  o);
                Sf  += __shfl_xor_sync(0xffffffffu, Sf,  o);
                Sfz += __shfl_xor_sync(0xffffffffu, Sfz, o);
            }
            float term = (Mfz + logf(Sfz)) - (Mf + logf(Sf)) - (Mz + logf(Sz)) + lognorm;
            if (term > 0.0f) tsum += term;
        }

        if (lane == 0) Ws[wq] = tsum;
    }
    __syncthreads();
    if (tid == 0) {
        float s = 0.0f;
        #pragma unroll
        for (int q = 0; q < 8; q++) s += Ws[q];
        g_partial[blockIdx.x] = s;
    }

    // ---- last block: deterministic final reduction ----
    __shared__ int isLast;
    __threadfence();
    __syncthreads();
    if (tid == 0) isLast = (atomicAdd(&g_count, 1) == NT * 4 - 1);
    __syncthreads();
    if (isLast) {
        if (tid < 128) Xs[tid] = g_partial[tid];
        __syncthreads();
        if (tid < 32) {
            float s = Xs[tid] + Xs[tid + 32] + Xs[tid + 64] + Xs[tid + 96];
            #pragma unroll
            for (int o = 16; o > 0; o >>= 1) s += __shfl_xor_sync(0xffffffffu, s, o);
            if (tid == 0) {
                out[0] = s * (1.0f / (float)(NT * NB));
                g_count = 0;
            }
        }
    }
}

// ---------------------------------------------------------------------------
extern "C" void kernel_launch(void* const* d_in, const int* in_sizes, int n_in,
                              void* d_out, int out_size) {
    const float* fm  = (const float*)d_in[0];
    const float* flv = (const float*)d_in[1];
    const float* fs  = (const float*)d_in[2];
    const float* zm  = (const float*)d_in[3];
    const float* zlv = (const float*)d_in[4];
    const float* zs  = (const float*)d_in[5];
    const int*   nt  = (const int*)  d_in[6];

    const size_t smem_pf = (size_t)(128 * 17 * 2 + 16 * 260 * 2) * sizeof(float);  // ~50 KB
    const size_t smem_kz = (size_t)(128 * 132 * 2 + 32 * 132 + 128 + 8 + 256 * 16 + 32 * 128)
                           * sizeof(float);                                        // ~185 KB

    static int inited = 0;
    if (!inited) {
        cudaFuncSetAttribute(pair_f, cudaFuncAttributeMaxDynamicSharedMemorySize, (int)smem_pf);
        cudaFuncSetAttribute(k_z,    cudaFuncAttributeMaxDynamicSharedMemorySize, (int)smem_kz);
        inited = 1;
    }

    prep_all<<<544, 256>>>(zm, zlv, fm, flv);
    pair_f<<<dim3(8, 8), 256, smem_pf>>>(fs);
    k_z<<<128, 512, smem_kz>>>(zs, nt, (float*)d_out);
}

// round 15
// speedup vs baseline: 1.5478x; 1.0685x over previous
#include <cuda_runtime.h>
#include <math.h>

#define NB   128
#define NT   32
#define DZv  128
#define DFv  256
#define LOG2PI_F 1.8378770664093453f

typedef unsigned long long ull;

// ----- device scratch -------------------------------------------------------
__device__ float g_Gf[NB * NB];          // f pairwise log-density (final)
__device__ float g_za[NT * NB * DZv];    // exp(-z_logvar)   [t][j][d]
__device__ float g_zb[NT * NB * DZv];    // -z_mean * za     [t][j][d]
__device__ float g_Cz[NT * NB];
__device__ float g_partial[NT * 4];
__device__ int   g_count = 0;

static __device__ __forceinline__ ull fma2(ull a, ull b, ull c) {
    ull d;
    asm("fma.rn.f32x2 %0, %1, %2, %3;" : "=l"(d) : "l"(a), "l"(b), "l"(c));
    return d;
}
static __device__ __forceinline__ float ull_sum2(ull v) {
    union { ull u; float2 f; } w; w.u = v;
    return w.f.x + w.f.y;
}

// ---------------------------------------------------------------------------
// prep_z: z exp transforms + row constants, MLP=8 per thread.
// 128 blocks x 256 threads. Block covers 32 rows (j,t); warp w covers rows
// [b*32 + w*4, +4); lane covers the 32 float4 of each 512B row.
// ---------------------------------------------------------------------------
__global__ void prep_z(const float* __restrict__ zm,
                       const float* __restrict__ zlv) {
    const int lane = threadIdx.x & 31, w = threadIdx.x >> 5;
    const int r0 = blockIdx.x * 32 + w * 4;

    float4 lv[4], mu[4];
    #pragma unroll
    for (int rr = 0; rr < 4; rr++) {
        lv[rr] = ((const float4*)zlv)[(r0 + rr) * 32 + lane];
        mu[rr] = ((const float4*)zm)[(r0 + rr) * 32 + lane];
    }
    #pragma unroll
    for (int rr = 0; rr < 4; rr++) {
        const int r = r0 + rr;
        const int j = r >> 5, t = r & 31;
        float4 a, b;
        a.x = __expf(-lv[rr].x); a.y = __expf(-lv[rr].y);
        a.z = __expf(-lv[rr].z); a.w = __expf(-lv[rr].w);
        b.x = -mu[rr].x * a.x;   b.y = -mu[rr].y * a.y;
        b.z = -mu[rr].z * a.z;   b.w = -mu[rr].w * a.w;
        ((float4*)g_za)[(t * NB + j) * 32 + lane] = a;
        ((float4*)g_zb)[(t * NB + j) * 32 + lane] = b;
        float s = lv[rr].x + lv[rr].y + lv[rr].z + lv[rr].w;
        #pragma unroll
        for (int o = 16; o > 0; o >>= 1) s += __shfl_xor_sync(0xffffffffu, s, o);
        if (lane == 0) g_Cz[t * NB + j] = 2.0f * s + (float)DZv * LOG2PI_F;
    }
}

// ---------------------------------------------------------------------------
// pair_f: f pairwise matrix with fused f-exp. grid (8,8)=64 blocks, 256 thr:
// i = tid&15, jj = tid>>4 — one output each.
// ---------------------------------------------------------------------------
__global__ void pair_f(const float* __restrict__ fm,
                       const float* __restrict__ flv,
                       const float* __restrict__ fs) {
    extern __shared__ float sm[];
    float2* st2 = (float2*)sm;             // 128*17 float2
    float*  As  = sm + 128 * 17 * 2;       // 16*260
    float*  Bs  = As + 16 * 260;           // 16*260
    float*  Csf = Bs + 16 * 260;           // 16

    const int tid = threadIdx.x;
    const int lane = tid & 31, w = tid >> 5;
    const int i0  = blockIdx.x * 16;
    const int j0  = blockIdx.y * 16;

    // samples d-pair-major: st2[d/2][i]
    for (int e = tid; e < 16 * DFv; e += 256) {
        int ii = e >> 8, d = e & 255;
        float v = fs[(i0 + ii) * DFv + d];
        ((float*)&st2[(d >> 1) * 17 + ii])[d & 1] = v;
    }
    // a/b tiles with fused exp
    for (int e = tid; e < 16 * DFv; e += 256) {
        int jj = e >> 8, d = e & 255;
        float lv = flv[(j0 + jj) * DFv + d];
        float a  = __expf(-lv);
        As[jj * 260 + d] = a;
        Bs[jj * 260 + d] = -fm[(j0 + jj) * DFv + d] * a;
    }
    // row constants: warp w -> rows w and w+8; lane covers 8 floats
    #pragma unroll
    for (int rq = 0; rq < 2; rq++) {
        const int r = w + 8 * rq;
        const float4* p = (const float4*)&flv[(j0 + r) * DFv + lane * 8];
        float4 v0 = p[0], v1 = p[1];
        float s = v0.x + v0.y + v0.z + v0.w + v1.x + v1.y + v1.z + v1.w;
        #pragma unroll
        for (int o = 16; o > 0; o >>= 1) s += __shfl_xor_sync(0xffffffffu, s, o);
        if (lane == 0) Csf[r] = 2.0f * s + (float)DFv * LOG2PI_F;
    }
    __syncthreads();

    const int i  = tid & 15;
    const int jj = tid >> 4;

    ull acc = 0ull;
    const ull* arow = (const ull*)&As[jj * 260];
    const ull* brow = (const ull*)&Bs[jj * 260];

    #pragma unroll 8
    for (int dp = 0; dp < DFv / 2; dp++) {
        ull s2 = ((const ull*)st2)[dp * 17 + i];
        ull t0 = fma2(s2, arow[dp], brow[dp]);
        acc = fma2(t0, t0, acc);
    }

    g_Gf[(i0 + i) * NB + j0 + jj] = -0.5f * (ull_sum2(acc) + Csf[jj]);
}

// ---------------------------------------------------------------------------
// k_z: z pairwise + logsumexps + relu + fused final reduction.
// grid 128 (t = bid&31, i-chunk = bid>>5), 512 threads = 16 warps.
// Warp w: h = w>>3 selects d-half; wq = w&7:
//   i in {wq + 8m} (broadcast s), j = lane + 32k (distinct a/b rows).
// Warp pair (wq, wq+8) combines complementary d-halves through smem.
// ---------------------------------------------------------------------------
__global__ void __launch_bounds__(512, 1)
k_z(const float* __restrict__ zs,
    const int*   __restrict__ ntp,
    float*       __restrict__ out) {
    extern __shared__ float sm[];
    float* As = sm;                  // 128*132
    float* Bs = As + 128 * 132;      // 128*132
    float* Ss = Bs + 128 * 132;      // 32*132
    float* Cs = Ss + 32 * 132;       // 128
    float* Ws = Cs + 128;            // 8
    float* Xs = Ws + 8;              // 256*16 (half-combine + final reduce)
    float* Gs = Xs + 256 * 16;       // 32*128 (Gf tile)

    const int tid  = threadIdx.x;
    const int t    = blockIdx.x & 31;
    const int i0   = (blockIdx.x >> 5) * 32;
    const int lane = tid & 31;
    const int w    = tid >> 5;           // 0..15
    const int h    = w >> 3;             // d-half
    const int wq   = w & 7;              // tile row-group

    // ---- staging: fully contiguous [t][j][d] slabs ----
    const float* zaT = &g_za[t * (NB * DZv)];
    const float* zbT = &g_zb[t * (NB * DZv)];
    for (int e = tid; e < 128 * 32; e += 512) {
        int jj = e >> 5, dq = e & 31;
        *(float4*)&As[jj * 132 + dq * 4] = *(const float4*)&zaT[jj * DZv + dq * 4];
        *(float4*)&Bs[jj * 132 + dq * 4] = *(const float4*)&zbT[jj * DZv + dq * 4];
    }
    for (int e = tid; e < 32 * 32; e += 512) {
        int ii = e >> 5, dq = e & 31;
        *(float4*)&Ss[ii * 132 + dq * 4] =
            *(const float4*)&zs[(i0 + ii) * (NT * DZv) + t * DZv + dq * 4];
    }
    for (int e = tid; e < 32 * 32; e += 512) {
        *(float4*)&Gs[e * 4] = *(const float4*)&g_Gf[i0 * NB + e * 4];
    }
    if (tid < 128) Cs[tid] = g_Cz[t * NB + tid];
    __syncthreads();

    // ---- main loop over this warp's d-half (single packed acc per tile) ----
    ull acc[4][4];
    #pragma unroll
    for (int m = 0; m < 4; m++)
        #pragma unroll
        for (int k = 0; k < 4; k++) acc[m][k] = 0ull;

    const int d0 = h * 64;
    #pragma unroll 4
    for (int dd = 0; dd < 64; dd += 4) {
        const int d = d0 + dd;
        ulonglong2 s2[4], a2[4], b2[4];
        #pragma unroll
        for (int m = 0; m < 4; m++)
            s2[m] = *(const ulonglong2*)&Ss[(wq + 8 * m) * 132 + d];    // broadcast
        #pragma unroll
        for (int k = 0; k < 4; k++) {
            a2[k] = *(const ulonglong2*)&As[(lane + 32 * k) * 132 + d];
            b2[k] = *(const ulonglong2*)&Bs[(lane + 32 * k) * 132 + d];
        }
        #pragma unroll
        for (int m = 0; m < 4; m++) {
            #pragma unroll
            for (int k = 0; k < 4; k++) {
                ull t0 = fma2(s2[m].x, a2[k].x, b2[k].x);
                ull t1 = fma2(s2[m].y, a2[k].y, b2[k].y);
                acc[m][k] = fma2(t0, t0, acc[m][k]);
                acc[m][k] = fma2(t1, t1, acc[m][k]);
            }
        }
    }

    float sums[4][4];
    #pragma unroll
    for (int m = 0; m < 4; m++)
        #pragma unroll
        for (int k = 0; k < 4; k++)
            sums[m][k] = ull_sum2(acc[m][k]);

    // ---- combine d-halves through smem ----
    if (h == 1) {
        float* x = &Xs[(tid - 256) * 16];
        #pragma unroll
        for (int m = 0; m < 4; m++)
            #pragma unroll
            for (int k = 0; k < 4; k++) x[m * 4 + k] = sums[m][k];
    }
    __syncthreads();

    if (h == 0) {
        const float* x = &Xs[tid * 16];
        #pragma unroll
        for (int m = 0; m < 4; m++)
            #pragma unroll
            for (int k = 0; k < 4; k++) sums[m][k] += x[m * 4 + k];

        // ---- epilogue: per-row logsumexps (row group in one warp) ----
        const float lognorm = logf(128.0f) + logf((float)ntp[0]);
        float tsum = 0.0f;

        #pragma unroll
        for (int m = 0; m < 4; m++) {
            const int il = wq + 8 * m;
            float vz[4], vf[4], vfz[4];
            #pragma unroll
            for (int k = 0; k < 4; k++) {
                int j = lane + 32 * k;
                vz[k]  = -0.5f * (sums[m][k] + Cs[j]);
                vf[k]  = Gs[il * NB + j];
                vfz[k] = vz[k] + vf[k];
            }
            float Mz  = fmaxf(fmaxf(vz[0],  vz[1]),  fmaxf(vz[2],  vz[3]));
            float Mf  = fmaxf(fmaxf(vf[0],  vf[1]),  fmaxf(vf[2],  vf[3]));
            float Mfz = fmaxf(fmaxf(vfz[0], vfz[1]), fmaxf(vfz[2], vfz[3]));
            #pragma unroll
            for (int o = 16; o > 0; o >>= 1) {
                Mz  = fmaxf(Mz,  __shfl_xor_sync(0xffffffffu, Mz,  o));
                Mf  = fmaxf(Mf,  __shfl_xor_sync(0xffffffffu, Mf,  o));
                Mfz = fmaxf(Mfz, __shfl_xor_sync(0xffffffffu, Mfz, o));
            }
            float Sz  = __expf(vz[0]  - Mz)  + __expf(vz[1]  - Mz)
                      + __expf(vz[2]  - Mz)  + __expf(vz[3]  - Mz);
            float Sf  = __expf(vf[0]  - Mf)  + __expf(vf[1]  - Mf)
                      + __expf(vf[2]  - Mf)  + __expf(vf[3]  - Mf);
            float Sfz = __expf(vfz[0] - Mfz) + __expf(vfz[1] - Mfz)
                      + __expf(vfz[2] - Mfz) + __expf(vfz[3] - Mfz);
            #pragma unroll
            for (int o = 16; o > 0; o >>= 1) {
                Sz  += __shfl_xor_sync(0xffffffffu, Sz,  o);
                Sf  += __shfl_xor_sync(0xffffffffu, Sf,  o);
                Sfz += __shfl_xor_sync(0xffffffffu, Sfz, o);
            }
            float term = (Mfz + __logf(Sfz)) - (Mf + __logf(Sf)) - (Mz + __logf(Sz)) + lognorm;
            if (term > 0.0f) tsum += term;
        }

        if (lane == 0) Ws[wq] = tsum;
    }
    __syncthreads();
    if (tid == 0) {
        float s = 0.0f;
        #pragma unroll
        for (int q = 0; q < 8; q++) s += Ws[q];
        g_partial[blockIdx.x] = s;
    }

    // ---- last block: deterministic final reduction ----
    __shared__ int isLast;
    __threadfence();
    __syncthreads();
    if (tid == 0) isLast = (atomicAdd(&g_count, 1) == NT * 4 - 1);
    __syncthreads();
    if (isLast) {
        if (tid < 128) Xs[tid] = g_partial[tid];
        __syncthreads();
        if (tid < 32) {
            float s = Xs[tid] + Xs[tid + 32] + Xs[tid + 64] + Xs[tid + 96];
            #pragma unroll
            for (int o = 16; o > 0; o >>= 1) s += __shfl_xor_sync(0xffffffffu, s, o);
            if (tid == 0) {
                out[0] = s * (1.0f / (float)(NT * NB));
                g_count = 0;
            }
        }
    }
}

// ---------------------------------------------------------------------------
extern "C" void kernel_launch(void* const* d_in, const int* in_sizes, int n_in,
                              void* d_out, int out_size) {
    const float* fm  = (const float*)d_in[0];
    const float* flv = (const float*)d_in[1];
    const float* fs  = (const float*)d_in[2];
    const float* zm  = (const float*)d_in[3];
    const float* zlv = (const float*)d_in[4];
    const float* zs  = (const float*)d_in[5];
    const int*   nt  = (const int*)  d_in[6];

    const size_t smem_pf = (size_t)(128 * 17 * 2 + 16 * 260 * 2 + 16) * sizeof(float);  // ~50 KB
    const size_t smem_kz = (size_t)(128 * 132 * 2 + 32 * 132 + 128 + 8 + 256 * 16 + 32 * 128)
                           * sizeof(float);                                             // ~185 KB

    static int inited = 0;
    if (!inited) {
        cudaFuncSetAttribute(pair_f, cudaFuncAttributeMaxDynamicSharedMemorySize, (int)smem_pf);
        cudaFuncSetAttribute(k_z,    cudaFuncAttributeMaxDynamicSharedMemorySize, (int)smem_kz);
        inited = 1;
    }

    prep_z<<<128, 256>>>(zm, zlv);
    pair_f<<<dim3(8, 8), 256, smem_pf>>>(fm, flv, fs);
    k_z<<<128, 512, smem_kz>>>(zs, nt, (float*)d_out);
}